// round 3
// baseline (speedup 1.0000x reference)
#include <cuda_runtime.h>

// Problem constants
#define Cc   128
#define Hh   128
#define Ww   256
#define Bb   8
#define Kk   9
#define CSTRIDE (Hh * Ww)          // 32768  (channel stride in elements)
#define BSTRIDE (Cc * Hh * Ww)     // 4194304 (batch stride in elements)

// One recurrence step:
//   cur[b,co,p] = cur_old[b,co,p] + relu( sum_{ci,k} W[co,ci,k] * prev[b,ci,p+k-4] )
// where p runs along the conv axis (stride SP, length L) and q (prev/cur index)
// runs along the recurrence axis (stride SQ). Zero padding at the p boundaries.
//
// TP = per-thread p-tile (4 for W-conv where L=256, 2 for H-conv where L=128).
// CTA: 256 threads = 16 co-groups x 16 p-groups; each thread computes 2 co x TP p.
// CTA tile: 32 co x (16*TP) p. Grid: (L/(16*TP), 128/32, B) = (4,4,8) = 128 CTAs.
template <int TP>
__global__ __launch_bounds__(256)
void step_kernel(float* __restrict__ state,
                 const float* __restrict__ wt,
                 int q_prev, int q_cur, int L, int SP, int SQ)
{
    constexpr int PT  = 16 * TP;     // CTA p extent (64 or 32)
    constexpr int WIN = PT + 8;      // staged input window (72 or 40)
    constexpr int CIC = 16;          // ci chunk

    __shared__ __align__(16) float s_in[CIC][WIN];
    __shared__ __align__(16) float s_w[32 * CIC * 12];   // [co][ci][12] padded rows

    const int tid = threadIdx.x;
    const int pg  = tid & 15;        // p group 0..15
    const int cg  = tid >> 4;        // co group 0..15

    const int p0  = blockIdx.x * PT;
    const int co0 = blockIdx.y * 32;
    const int b   = blockIdx.z;

    const float* prev = state + (long)b * BSTRIDE + (long)q_prev * SQ;
    float*       cur  = state + (long)b * BSTRIDE + (long)q_cur  * SQ;

    float acc[2][TP];
#pragma unroll
    for (int c = 0; c < 2; c++)
#pragma unroll
        for (int pt = 0; pt < TP; pt++) acc[c][pt] = 0.f;

    for (int cic = 0; cic < Cc; cic += CIC) {
        // ---- stage weight chunk: s_w[co][ci][k], co in [0,32), ci in [0,16) ----
        for (int idx = tid; idx < 32 * CIC * Kk; idx += 256) {
            int co = idx / (CIC * Kk);
            int r  = idx - co * (CIC * Kk);
            int ci = r / Kk;
            int k  = r - ci * Kk;
            s_w[(co * CIC + ci) * 12 + k] =
                wt[(long)(co0 + co) * (Cc * Kk) + (long)(cic + ci) * Kk + k];
        }
        // ---- stage input windows: s_in[ci][pl], global p = p0-4+pl, zero-padded ----
        for (int idx = tid; idx < CIC * WIN; idx += 256) {
            int ci = idx / WIN;
            int pl = idx - ci * WIN;
            int p  = p0 - 4 + pl;
            float v = 0.f;
            if (p >= 0 && p < L)
                v = prev[(long)(cic + ci) * CSTRIDE + (long)p * SP];
            s_in[ci][pl] = v;
        }
        __syncthreads();

        // ---- compute ----
#pragma unroll 4
        for (int ci = 0; ci < CIC; ci++) {
            float v[TP + 8];
            if constexpr (TP == 4) {
                const float4* s4 = reinterpret_cast<const float4*>(&s_in[ci][pg * 4]);
                float4 a = s4[0], bb = s4[1], cc = s4[2];
                v[0]=a.x;  v[1]=a.y;  v[2]=a.z;  v[3]=a.w;
                v[4]=bb.x; v[5]=bb.y; v[6]=bb.z; v[7]=bb.w;
                v[8]=cc.x; v[9]=cc.y; v[10]=cc.z; v[11]=cc.w;
            } else {
                const float2* s2 = reinterpret_cast<const float2*>(&s_in[ci][pg * 2]);
#pragma unroll
                for (int j = 0; j < 5; j++) {
                    float2 t = s2[j];
                    v[2 * j] = t.x; v[2 * j + 1] = t.y;
                }
            }
#pragma unroll
            for (int c = 0; c < 2; c++) {
                const int co_l = cg * 2 + c;
                const float4* w4 =
                    reinterpret_cast<const float4*>(&s_w[(co_l * CIC + ci) * 12]);
                float4 wa = w4[0], wb = w4[1], wc = w4[2];
                float wr[9] = {wa.x, wa.y, wa.z, wa.w, wb.x, wb.y, wb.z, wb.w, wc.x};
#pragma unroll
                for (int pt = 0; pt < TP; pt++) {
#pragma unroll
                    for (int k = 0; k < Kk; k++)
                        acc[c][pt] += wr[k] * v[pt + k];
                }
            }
        }
        __syncthreads();
    }

    // ---- epilogue: cur = cur_old + relu(conv) ----
#pragma unroll
    for (int c = 0; c < 2; c++) {
        const int co_l = cg * 2 + c;
#pragma unroll
        for (int pt = 0; pt < TP; pt++) {
            const int p = p0 + pg * TP + pt;
            const long off = (long)(co0 + co_l) * CSTRIDE + (long)p * SP;
            const float old = cur[off];
            cur[off] = old + fmaxf(acc[c][pt], 0.f);
        }
    }
}

extern "C" void kernel_launch(void* const* d_in, const int* in_sizes, int n_in,
                              void* d_out, int out_size)
{
    const float* x       = (const float*)d_in[0];
    const float* w_down  = (const float*)d_in[1];
    const float* w_up    = (const float*)d_in[2];
    const float* w_right = (const float*)d_in[3];
    const float* w_left  = (const float*)d_in[4];
    float* out = (float*)d_out;

    // state := x (in-place recurrences after this)
    cudaMemcpyAsync(out, x, (size_t)Bb * BSTRIDE * sizeof(float),
                    cudaMemcpyDeviceToDevice);

    dim3 blk(256);
    dim3 gridW(Ww / 64, Cc / 32, Bb);   // (4,4,8) for conv along W (TP=4)
    dim3 gridH(Hh / 32, Cc / 32, Bb);   // (4,4,8) for conv along H (TP=2)

    // Pass 1: down (axis H, forward), conv along W: L=256, SP=1, SQ=W
    for (int i = 1; i < Hh; i++)
        step_kernel<4><<<gridW, blk>>>(out, w_down, i - 1, i, Ww, 1, Ww);

    // Pass 2: up (axis H, reverse): out[i] = y[i] + relu(conv(out[i+1]))
    for (int i = Hh - 2; i >= 0; i--)
        step_kernel<4><<<gridW, blk>>>(out, w_up, i + 1, i, Ww, 1, Ww);

    // Pass 3: right (axis W, forward), conv along H: L=128, SP=W, SQ=1
    for (int j = 1; j < Ww; j++)
        step_kernel<2><<<gridH, blk>>>(out, w_right, j - 1, j, Hh, Ww, 1);

    // Pass 4: left (axis W, reverse)
    for (int j = Ww - 2; j >= 0; j--)
        step_kernel<2><<<gridH, blk>>>(out, w_left, j + 1, j, Hh, Ww, 1);
}

// round 4
// speedup vs baseline: 2.1661x; 2.1661x over previous
#include <cuda_runtime.h>

#define Cc 128
#define Hh 128
#define Ww 256
#define Bb 8
#define Kk 9
#define CSTRIDE (Hh * Ww)          // 32768
#define BSTRIDE (Cc * Hh * Ww)     // 4194304
#define NCTA 128u

// Grid-barrier state: [0] = arrival counter (monotonic per launch), [1] = release flag.
// Reset to 0 by cudaMemsetAsync before each pass kernel.
__device__ unsigned g_bar[2];

__device__ __forceinline__ void grid_barrier(unsigned gen) {
    __threadfence();           // publish this thread's STGs device-wide
    __syncthreads();           // all threads of CTA fenced & done
    if (threadIdx.x == 0) {
        unsigned t = atomicAdd(&g_bar[0], 1u);
        if (t == gen * NCTA + (NCTA - 1u)) {
            atomicExch(&g_bar[1], gen + 1u);      // release
        } else {
            volatile unsigned* f = &g_bar[1];
            while (*f < gen + 1u) __nanosleep(64);
        }
    }
    __syncthreads();
}

// Persistent pass kernel. One CTA = (p-block, co-block, batch), fixed for the
// whole pass. Weights staged to SMEM once; recurrence steps separated by a
// grid barrier. Per step:
//   cur[co,p] = cur_old[co,p] + relu( sum_{ci,k} W[co,ci,k] * prev[ci, p+k-4] )
// p axis: length L, stride SP. q (recurrence) axis: stride SQ, from q0 by dq.
template <int TP>
__global__ __launch_bounds__(256)
void pass_kernel(float* __restrict__ state, const float* __restrict__ wt,
                 int q0, int dq, int nq, int L, int SP, int SQ)
{
    constexpr int PT  = 16 * TP;      // CTA p extent (64 or 32)
    constexpr int WIN = PT + 8;       // staged window (72 or 40)

    extern __shared__ float sm[];
    float* s_w8 = sm;                         // [32co][128ci][8]  (float4-aligned)
    float* s_w1 = sm + 32 * 128 * 8;          // [32co][128ci]     (9th tap)
    float* s_in = s_w1 + 32 * 128;            // [128ci][WIN]

    const int tid = threadIdx.x;
    const int pg  = tid & 15;                 // p group 0..15
    const int cg  = tid >> 4;                 // co group 0..15

    const int p0  = blockIdx.x * PT;
    const int co0 = blockIdx.y * 32;
    const int b   = blockIdx.z;
    float* base = state + (long)b * BSTRIDE;

    // ---- stage this co-block's weights once for the whole pass ----
    for (int idx = tid; idx < 32 * 128; idx += 256) {
        int co = idx >> 7, ci = idx & 127;
        const float* g = wt + (long)(co0 + co) * (Cc * Kk) + ci * Kk;
#pragma unroll
        for (int k = 0; k < 8; k++) s_w8[idx * 8 + k] = g[k];
        s_w1[idx] = g[8];
    }
    __syncthreads();

    unsigned gen = 0;
    for (int s = 1; s < nq; s++) {
        if (s > 1) { grid_barrier(gen); gen++; }

        const int q_cur = q0 + s * dq;
        const float* prev = base + (long)(q_cur - dq) * SQ;
        float*       cur  = base + (long)q_cur * SQ;

        // ---- stage prev-row window: s_in[ci][pl], p = p0-4+pl, zero padded ----
        for (int idx = tid; idx < Cc * WIN; idx += 256) {
            int ci = idx / WIN;
            int pl = idx - ci * WIN;
            int p  = p0 - 4 + pl;
            float v = 0.f;
            if ((unsigned)p < (unsigned)L)
                v = __ldcg(prev + (long)ci * CSTRIDE + (long)p * SP);
            s_in[idx] = v;
        }
        __syncthreads();

        // ---- compute: 2 co x TP p per thread, full 128-ci reduction ----
        float acc[2][TP];
#pragma unroll
        for (int c = 0; c < 2; c++)
#pragma unroll
            for (int pt = 0; pt < TP; pt++) acc[c][pt] = 0.f;

#pragma unroll 2
        for (int ci = 0; ci < Cc; ci++) {
            float v[TP + 8];
            if constexpr (TP == 4) {
                const float4* s4 =
                    reinterpret_cast<const float4*>(&s_in[ci * WIN + pg * 4]);
                float4 a = s4[0], bb = s4[1], cc = s4[2];
                v[0]=a.x;  v[1]=a.y;  v[2]=a.z;  v[3]=a.w;
                v[4]=bb.x; v[5]=bb.y; v[6]=bb.z; v[7]=bb.w;
                v[8]=cc.x; v[9]=cc.y; v[10]=cc.z; v[11]=cc.w;
            } else {
                const float2* s2 =
                    reinterpret_cast<const float2*>(&s_in[ci * WIN + pg * 2]);
#pragma unroll
                for (int j = 0; j < 5; j++) {
                    float2 t = s2[j];
                    v[2 * j] = t.x; v[2 * j + 1] = t.y;
                }
            }
#pragma unroll
            for (int c = 0; c < 2; c++) {
                const int widx = (cg * 2 + c) * 128 + ci;
                const float4 wa = *reinterpret_cast<const float4*>(s_w8 + widx * 8);
                const float4 wb = *reinterpret_cast<const float4*>(s_w8 + widx * 8 + 4);
                const float  w8 = s_w1[widx];
                const float wr[9] = {wa.x, wa.y, wa.z, wa.w,
                                     wb.x, wb.y, wb.z, wb.w, w8};
#pragma unroll
                for (int pt = 0; pt < TP; pt++)
#pragma unroll
                    for (int k = 0; k < Kk; k++)
                        acc[c][pt] = fmaf(wr[k], v[pt + k], acc[c][pt]);
            }
        }

        // ---- epilogue: cur = cur_old + relu(conv) ----
#pragma unroll
        for (int c = 0; c < 2; c++) {
            const int co_l = cg * 2 + c;
#pragma unroll
            for (int pt = 0; pt < TP; pt++) {
                const int  p   = p0 + pg * TP + pt;
                const long off = (long)(co0 + co_l) * CSTRIDE + (long)p * SP;
                cur[off] = __ldcg(cur + off) + fmaxf(acc[c][pt], 0.f);
            }
        }
    }
}

extern "C" void kernel_launch(void* const* d_in, const int* in_sizes, int n_in,
                              void* d_out, int out_size)
{
    const float* x       = (const float*)d_in[0];
    const float* w_down  = (const float*)d_in[1];
    const float* w_up    = (const float*)d_in[2];
    const float* w_right = (const float*)d_in[3];
    const float* w_left  = (const float*)d_in[4];
    float* out = (float*)d_out;

    const int SMEM4 = (32 * 128 * 8 + 32 * 128 + 128 * 72) * 4;  // 184320 B
    const int SMEM2 = (32 * 128 * 8 + 32 * 128 + 128 * 40) * 4;  // 167936 B
    cudaFuncSetAttribute((const void*)pass_kernel<4>,
                         cudaFuncAttributeMaxDynamicSharedMemorySize, SMEM4);
    cudaFuncSetAttribute((const void*)pass_kernel<2>,
                         cudaFuncAttributeMaxDynamicSharedMemorySize, SMEM2);

    void* barp = nullptr;
    cudaGetSymbolAddress(&barp, g_bar);

    // state := x
    cudaMemcpyAsync(out, x, (size_t)Bb * BSTRIDE * sizeof(float),
                    cudaMemcpyDeviceToDevice);

    dim3 blk(256);
    dim3 gridW(Ww / 64, Cc / 32, Bb);   // (4,4,8) = 128 CTAs, conv along W
    dim3 gridH(Hh / 32, Cc / 32, Bb);   // (4,4,8) = 128 CTAs, conv along H

    // Pass 1: down (q over H, forward), conv along W: L=256, SP=1, SQ=W
    cudaMemsetAsync(barp, 0, 2 * sizeof(unsigned));
    pass_kernel<4><<<gridW, blk, SMEM4>>>(out, w_down, 0, +1, Hh, Ww, 1, Ww);

    // Pass 2: up (q over H, reverse)
    cudaMemsetAsync(barp, 0, 2 * sizeof(unsigned));
    pass_kernel<4><<<gridW, blk, SMEM4>>>(out, w_up, Hh - 1, -1, Hh, Ww, 1, Ww);

    // Pass 3: right (q over W, forward), conv along H: L=128, SP=W, SQ=1
    cudaMemsetAsync(barp, 0, 2 * sizeof(unsigned));
    pass_kernel<2><<<gridH, blk, SMEM2>>>(out, w_right, 0, +1, Ww, Hh, Ww, 1);

    // Pass 4: left (q over W, reverse)
    cudaMemsetAsync(barp, 0, 2 * sizeof(unsigned));
    pass_kernel<2><<<gridH, blk, SMEM2>>>(out, w_left, Ww - 1, -1, Ww, Hh, Ww, 1);
}

// round 5
// speedup vs baseline: 2.7877x; 1.2869x over previous
#include <cuda_runtime.h>

#define Cc 128
#define Hh 128
#define Ww 256
#define Bb 8
#define Kk 9
#define CSTRIDE (Hh * Ww)          // 32768
#define BSTRIDE (Cc * Hh * Ww)     // 4194304

// Per-batch grid barrier: [b][0] = arrival counter, [b][1] = release generation.
__device__ unsigned g_bar[Bb][2];
// Transposed-state scratch: [b][c][w][h]
__device__ float g_tmp[(size_t)Bb * BSTRIDE];

// ---------- f32x2 helpers (sm_103a packed fp32 FMA) ----------
__device__ __forceinline__ unsigned long long splat2(float v) {
    unsigned long long r;
    asm("mov.b64 %0, {%1, %1};" : "=l"(r) : "f"(v));
    return r;
}
__device__ __forceinline__ void fma2(unsigned long long& d,
                                     unsigned long long a, unsigned long long b) {
    asm("fma.rn.f32x2 %0, %1, %2, %0;" : "+l"(d) : "l"(a), "l"(b));
}
__device__ __forceinline__ float2 unpack2(unsigned long long v) {
    float2 f;
    asm("mov.b64 {%0, %1}, %2;" : "=f"(f.x), "=f"(f.y) : "l"(v));
    return f;
}

// 16 CTAs participate per batch (gridDim.x * gridDim.y == 16).
__device__ __forceinline__ void grid_barrier_b(int b, unsigned gen) {
    __threadfence();
    __syncthreads();
    if (threadIdx.x == 0) {
        unsigned t = atomicAdd(&g_bar[b][0], 1u);
        if (t == gen * 16u + 15u) {
            atomicExch(&g_bar[b][1], gen + 1u);
        } else {
            volatile unsigned* f = &g_bar[b][1];
            while (*f <= gen) __nanosleep(32);
        }
    }
    __syncthreads();
}

// Weight SMEM layout: per cg (16 co-pairs), per ci: 20 floats (9 pairs + 2 pad),
// pairs are (w[co0][k], w[co1][k]) so LDS.64/LDS.128 yield packed f32x2 operands.
// cg stride padded (+8 floats) to avoid bank aliasing between the 2 cg's of a warp.
#define WCI_STRIDE 20
#define WCG_STRIDE (128 * WCI_STRIDE + 8)   // 2568 floats
#define W_FLOATS   (16 * WCG_STRIDE)        // 41088

// One directional pass, persistent. conv axis is CONTIGUOUS (SP=1, length L),
// recurrence axis has stride SQ, from q0 stepping dq, nq rows total.
// CTA = 256 thr = 16 pg x 16 cg; thread computes co-pair (2) x TP p outputs.
template <int TP>
__global__ __launch_bounds__(256)
void pass_kernel(float* __restrict__ state, const float* __restrict__ wt,
                 int q0, int dq, int nq, int L, int SQ)
{
    constexpr int PT  = 16 * TP;   // 64 (W-pass) or 32 (H-pass)
    constexpr int WIN = PT + 8;

    extern __shared__ float sm[];
    float* s_w  = sm;              // paired weights
    float* s_in = sm + W_FLOATS;   // [128ci][WIN]

    const int tid = threadIdx.x;
    const int pg  = tid & 15;
    const int cg  = tid >> 4;

    const int p0  = blockIdx.x * PT;
    const int co0 = blockIdx.y * 32;
    const int b   = blockIdx.z;
    float* base = state + (long)b * BSTRIDE;

    // ---- stage paired weights once ----
    for (int idx = tid; idx < 16 * 128 * Kk; idx += 256) {
        int cgi = idx / (128 * Kk);
        int r   = idx - cgi * (128 * Kk);
        int ci  = r / Kk;
        int k   = r - ci * Kk;
        const float* g = wt + (long)(co0 + cgi * 2) * (Cc * Kk) + ci * Kk + k;
        float* dst = s_w + cgi * WCG_STRIDE + ci * WCI_STRIDE + k * 2;
        dst[0] = g[0];            // co even
        dst[1] = g[Cc * Kk];      // co odd
    }
    __syncthreads();

    const float* wrow = s_w + cg * WCG_STRIDE;

    unsigned gen = 0;
    for (int s = 1; s < nq; s++) {
        if (s > 1) { grid_barrier_b(b, gen); gen++; }

        const int q = q0 + s * dq;
        const float* prev = base + (long)(q - dq) * SQ;
        float*       cur  = base + (long)q * SQ;

        // ---- stage prev row window (contiguous, coalesced) ----
        for (int idx = tid; idx < Cc * WIN; idx += 256) {
            int ci = idx / WIN;
            int pl = idx - ci * WIN;
            int p  = p0 - 4 + pl;
            float v = 0.f;
            if ((unsigned)p < (unsigned)L)
                v = __ldcg(prev + (long)ci * CSTRIDE + p);
            s_in[idx] = v;
        }

        // ---- prefetch cur_old (stable until we write it this step) ----
        float oldv[2][TP];
#pragma unroll
        for (int c = 0; c < 2; c++)
#pragma unroll
            for (int pt = 0; pt < TP; pt++)
                oldv[c][pt] = __ldcg(cur + (long)(co0 + cg * 2 + c) * CSTRIDE
                                         + p0 + pg * TP + pt);
        __syncthreads();

        // ---- compute: acc[pt] packs (co_even, co_odd) ----
        unsigned long long acc[TP];
#pragma unroll
        for (int pt = 0; pt < TP; pt++) acc[pt] = 0ull;

#pragma unroll 2
        for (int ci = 0; ci < Cc; ci++) {
            // input window -> splats
            float v[TP + 8];
            if constexpr (TP == 4) {
                const float4* s4 =
                    reinterpret_cast<const float4*>(&s_in[ci * WIN + pg * 4]);
                float4 a = s4[0], bb = s4[1], cc = s4[2];
                v[0]=a.x;  v[1]=a.y;  v[2]=a.z;  v[3]=a.w;
                v[4]=bb.x; v[5]=bb.y; v[6]=bb.z; v[7]=bb.w;
                v[8]=cc.x; v[9]=cc.y; v[10]=cc.z; v[11]=cc.w;
            } else {
                const float2* s2 =
                    reinterpret_cast<const float2*>(&s_in[ci * WIN + pg * 2]);
#pragma unroll
                for (int j = 0; j < 5; j++) {
                    float2 t = s2[j];
                    v[2 * j] = t.x; v[2 * j + 1] = t.y;
                }
            }
            unsigned long long sv[TP + 8];
#pragma unroll
            for (int j = 0; j < TP + 8; j++) sv[j] = splat2(v[j]);

            // packed weights: 9 x u64 (aligned: ci*20*4 = 80B, 16B-aligned)
            const float* wp = wrow + ci * WCI_STRIDE;
            unsigned long long ww[9];
            {
                const ulonglong2* w2 = reinterpret_cast<const ulonglong2*>(wp);
                ulonglong2 q0_ = w2[0], q1_ = w2[1], q2_ = w2[2], q3_ = w2[3];
                ww[0]=q0_.x; ww[1]=q0_.y; ww[2]=q1_.x; ww[3]=q1_.y;
                ww[4]=q2_.x; ww[5]=q2_.y; ww[6]=q3_.x; ww[7]=q3_.y;
                ww[8]=reinterpret_cast<const unsigned long long*>(wp)[4 * 2];
            }
#pragma unroll
            for (int pt = 0; pt < TP; pt++)
#pragma unroll
                for (int k = 0; k < Kk; k++)
                    fma2(acc[pt], ww[k], sv[pt + k]);
        }

        // ---- epilogue ----
#pragma unroll
        for (int pt = 0; pt < TP; pt++) {
            float2 r = unpack2(acc[pt]);
            const int  p = p0 + pg * TP + pt;
            const long o0 = (long)(co0 + cg * 2) * CSTRIDE + p;
            cur[o0]           = oldv[0][pt] + fmaxf(r.x, 0.f);
            cur[o0 + CSTRIDE] = oldv[1][pt] + fmaxf(r.y, 0.f);
        }
    }
}

// [b,c,R,C] -> [b,c,C,R], tiled 32x32.
__global__ __launch_bounds__(256)
void transpose_kernel(const float* __restrict__ src, float* __restrict__ dst,
                      int R, int C)
{
    __shared__ float t[32][33];
    const long plane = blockIdx.z;
    const float* s = src + plane * (long)R * C;
    float*       d = dst + plane * (long)R * C;
    const int c0 = blockIdx.x * 32, r0 = blockIdx.y * 32;
    const int x = threadIdx.x & 31, y = threadIdx.x >> 5;   // 32 x 8
#pragma unroll
    for (int i = 0; i < 32; i += 8)
        t[y + i][x] = s[(long)(r0 + y + i) * C + c0 + x];
    __syncthreads();
#pragma unroll
    for (int i = 0; i < 32; i += 8)
        d[(long)(c0 + y + i) * R + r0 + x] = t[x][y + i];
}

extern "C" void kernel_launch(void* const* d_in, const int* in_sizes, int n_in,
                              void* d_out, int out_size)
{
    const float* x       = (const float*)d_in[0];
    const float* w_down  = (const float*)d_in[1];
    const float* w_up    = (const float*)d_in[2];
    const float* w_right = (const float*)d_in[3];
    const float* w_left  = (const float*)d_in[4];
    float* out = (float*)d_out;

    const int SMEM_W = (W_FLOATS + Cc * 72) * 4;   // 201216 B
    const int SMEM_H = (W_FLOATS + Cc * 40) * 4;   // 184832 B
    cudaFuncSetAttribute((const void*)pass_kernel<4>,
                         cudaFuncAttributeMaxDynamicSharedMemorySize, SMEM_W);
    cudaFuncSetAttribute((const void*)pass_kernel<2>,
                         cudaFuncAttributeMaxDynamicSharedMemorySize, SMEM_H);

    void* barp = nullptr;  cudaGetSymbolAddress(&barp, g_bar);
    void* tmpp = nullptr;  cudaGetSymbolAddress(&tmpp, g_tmp);
    float* tmp = (float*)tmpp;

    cudaMemcpyAsync(out, x, (size_t)Bb * BSTRIDE * sizeof(float),
                    cudaMemcpyDeviceToDevice);

    dim3 blk(256);
    dim3 gridW(Ww / 64, Cc / 32, Bb);   // (4,4,8) conv along W, TP=4
    dim3 gridH(Hh / 32, Cc / 32, Bb);   // (4,4,8) conv along H (transposed), TP=2

    // Pass 1: down. Layout [b,c,h,w]: conv axis w (L=256, contiguous), rec over h (SQ=256).
    cudaMemsetAsync(barp, 0, sizeof(g_bar));
    pass_kernel<4><<<gridW, blk, SMEM_W>>>(out, w_down, 0, +1, Hh, Ww, Ww);

    // Pass 2: up.
    cudaMemsetAsync(barp, 0, sizeof(g_bar));
    pass_kernel<4><<<gridW, blk, SMEM_W>>>(out, w_up, Hh - 1, -1, Hh, Ww, Ww);

    // Transpose to [b,c,w,h]
    transpose_kernel<<<dim3(Ww / 32, Hh / 32, Bb * Cc), blk>>>(out, tmp, Hh, Ww);

    // Pass 3: right. conv axis h (L=128, contiguous), rec over w (SQ=128).
    cudaMemsetAsync(barp, 0, sizeof(g_bar));
    pass_kernel<2><<<gridH, blk, SMEM_H>>>(tmp, w_right, 0, +1, Ww, Hh, Hh);

    // Pass 4: left.
    cudaMemsetAsync(barp, 0, sizeof(g_bar));
    pass_kernel<2><<<gridH, blk, SMEM_H>>>(tmp, w_left, Ww - 1, -1, Ww, Hh, Hh);

    // Transpose back to [b,c,h,w]
    transpose_kernel<<<dim3(Hh / 32, Ww / 32, Bb * Cc), blk>>>(tmp, out, Ww, Hh);
}

// round 7
// speedup vs baseline: 3.0344x; 1.0885x over previous
#include <cuda_runtime.h>

#define Cc 128
#define Hh 128
#define Ww 256
#define Bb 8
#define Kk 9
#define CSTRIDE (Hh * Ww)          // 32768
#define BSTRIDE (Cc * Hh * Ww)     // 4194304

typedef unsigned long long ull;

// Per-batch grid barrier: [b][0] = arrival counter, [b][1] = release generation.
__device__ unsigned g_bar[Bb][2];
// Transposed-state scratch: [b][c][w][h]
__device__ float g_tmp[(size_t)Bb * BSTRIDE];

// ---------- f32x2 helpers ----------
__device__ __forceinline__ ull splat2(float v) {
    ull r;
    asm("mov.b64 %0, {%1, %1};" : "=l"(r) : "f"(v));
    return r;
}
__device__ __forceinline__ void fma2(ull& d, ull a, ull b) {
    asm("fma.rn.f32x2 %0, %1, %2, %0;" : "+l"(d) : "l"(a), "l"(b));
}
__device__ __forceinline__ float2 unpack2(ull v) {
    float2 f;
    asm("mov.b64 {%0, %1}, %2;" : "=f"(f.x), "=f"(f.y) : "l"(v));
    return f;
}

// 16 CTAs participate per batch. Fence by the elected thread after
// __syncthreads (CG grid.sync pattern; cumulativity covers CTA writes).
__device__ __forceinline__ void grid_barrier_b(int b, unsigned gen) {
    __syncthreads();
    if (threadIdx.x == 0) {
        __threadfence();
        unsigned t = atomicAdd(&g_bar[b][0], 1u);
        if (t == gen * 16u + 15u) {
            atomicExch(&g_bar[b][1], gen + 1u);
        } else {
            volatile unsigned* f = &g_bar[b][1];
            while (*f <= gen) __nanosleep(32);
            __threadfence();
        }
    }
    __syncthreads();
}

// Paired-weight SMEM layout: per cg (16 co-pairs), per ci: 20 floats
// (9 (co_even,co_odd) pairs + 2 pad). cg stride padded by 8 floats.
#define WCI_STRIDE 20
#define WCG_STRIDE (128 * WCI_STRIDE + 8)   // 2568 floats
#define W_FLOATS   (16 * WCG_STRIDE)        // 41088

// Persistent directional pass. conv axis contiguous (length L), recurrence
// axis stride SQ from q0 step dq, nq rows. CTA = 256 thr = 16 pg x 16 cg;
// thread computes one co-pair x TP p outputs. Software-pipelined over ci.
template <int TP>
__global__ __launch_bounds__(256)
void pass_kernel(float* __restrict__ state, const float* __restrict__ wt,
                 int q0, int dq, int nq, int L, int SQ)
{
    constexpr int PT  = 16 * TP;       // 64 (W-pass) or 32 (H-pass)
    constexpr int WIN = PT + 16;       // padded +-8, 16B-aligned rows
    constexpr int NV4 = WIN / 4;       // float4 slots per ci row
    constexpr int NW  = TP + 8;        // per-thread window floats

    extern __shared__ float sm[];
    float* s_w  = sm;
    float* s_in = sm + W_FLOATS;       // [128ci][WIN]

    const int tid = threadIdx.x;
    const int pg  = tid & 15;
    const int cg  = tid >> 4;

    const int p0  = blockIdx.x * PT;
    const int co0 = blockIdx.y * 32;
    const int b   = blockIdx.z;
    float* base = state + (long)b * BSTRIDE;

    // ---- stage paired weights once per pass ----
    for (int idx = tid; idx < 16 * 128 * Kk; idx += 256) {
        int cgi = idx / (128 * Kk);
        int r   = idx - cgi * (128 * Kk);
        int ci  = r / Kk;
        int k   = r - ci * Kk;
        const float* g = wt + (long)(co0 + cgi * 2) * (Cc * Kk) + ci * Kk + k;
        float* dst = s_w + cgi * WCG_STRIDE + ci * WCI_STRIDE + k * 2;
        dst[0] = g[0];
        dst[1] = g[Cc * Kk];
    }
    __syncthreads();

    const float* wrow = s_w + cg * WCG_STRIDE;

    unsigned gen = 0;
    for (int s = 1; s < nq; s++) {
        if (s > 1) { grid_barrier_b(b, gen); gen++; }

        const int q = q0 + s * dq;
        const float* prev = base + (long)(q - dq) * SQ;
        float*       cur  = base + (long)q * SQ;

        // ---- stage prev-row window, float4-vectorized ----
        for (int idx = tid; idx < Cc * NV4; idx += 256) {
            const int ci = idx / NV4;
            const int c4 = idx - ci * NV4;
            const int p  = p0 - 8 + c4 * 4;
            const float* src = prev + (long)ci * CSTRIDE + p;
            float4 v;
            if (p >= 0 && p + 4 <= L) {
                v = __ldcg(reinterpret_cast<const float4*>(src));
            } else {
                v.x = (unsigned)(p + 0) < (unsigned)L ? __ldcg(src + 0) : 0.f;
                v.y = (unsigned)(p + 1) < (unsigned)L ? __ldcg(src + 1) : 0.f;
                v.z = (unsigned)(p + 2) < (unsigned)L ? __ldcg(src + 2) : 0.f;
                v.w = (unsigned)(p + 3) < (unsigned)L ? __ldcg(src + 3) : 0.f;
            }
            reinterpret_cast<float4*>(s_in)[idx] = v;
        }

        // ---- prefetch cur_old (this CTA's exclusive addresses) ----
        const long oBase = (long)(co0 + cg * 2) * CSTRIDE + p0 + pg * TP;
        float4 old4[2]; float2 old2[2];
        if constexpr (TP == 4) {
            old4[0] = __ldcg(reinterpret_cast<const float4*>(cur + oBase));
            old4[1] = __ldcg(reinterpret_cast<const float4*>(cur + oBase + CSTRIDE));
        } else {
            old2[0] = __ldcg(reinterpret_cast<const float2*>(cur + oBase));
            old2[1] = __ldcg(reinterpret_cast<const float2*>(cur + oBase + CSTRIDE));
        }
        __syncthreads();

        // ---- software-pipelined compute over ci ----
        float vb[2][NW];
        ull   wb[2][9];

        auto LOADCI = [&](int ci, int slot) {
            if constexpr (TP == 4) {
                const float4* s4 =
                    reinterpret_cast<const float4*>(&s_in[ci * WIN + pg * 4 + 4]);
                float4 a = s4[0], b2 = s4[1], c2 = s4[2];
                vb[slot][0]=a.x;  vb[slot][1]=a.y;  vb[slot][2]=a.z;  vb[slot][3]=a.w;
                vb[slot][4]=b2.x; vb[slot][5]=b2.y; vb[slot][6]=b2.z; vb[slot][7]=b2.w;
                vb[slot][8]=c2.x; vb[slot][9]=c2.y; vb[slot][10]=c2.z; vb[slot][11]=c2.w;
            } else {
                const float2* s2 =
                    reinterpret_cast<const float2*>(&s_in[ci * WIN + pg * 2 + 4]);
#pragma unroll
                for (int j = 0; j < 5; j++) {
                    float2 t = s2[j];
                    vb[slot][2 * j] = t.x; vb[slot][2 * j + 1] = t.y;
                }
            }
            const float* wp = wrow + ci * WCI_STRIDE;
            const ulonglong2* w2 = reinterpret_cast<const ulonglong2*>(wp);
            ulonglong2 qa = w2[0], qb = w2[1], qc = w2[2], qd = w2[3];
            wb[slot][0]=qa.x; wb[slot][1]=qa.y; wb[slot][2]=qb.x; wb[slot][3]=qb.y;
            wb[slot][4]=qc.x; wb[slot][5]=qc.y; wb[slot][6]=qd.x; wb[slot][7]=qd.y;
            wb[slot][8]=reinterpret_cast<const ull*>(wp)[8];   // k=8 pair (floats 16-17)
        };

        ull acc[TP];
#pragma unroll
        for (int pt = 0; pt < TP; pt++) acc[pt] = 0ull;

        auto FMACI = [&](int slot) {
            ull sv[NW];
#pragma unroll
            for (int j = 0; j < NW; j++) sv[j] = splat2(vb[slot][j]);
#pragma unroll
            for (int k = 0; k < Kk; k++)
#pragma unroll
                for (int pt = 0; pt < TP; pt++)
                    fma2(acc[pt], wb[slot][k], sv[pt + k]);
        };

        LOADCI(0, 0);
        for (int ci = 0; ci + 2 < Cc; ci += 2) {
            LOADCI(ci + 1, 1); FMACI(0);
            LOADCI(ci + 2, 0); FMACI(1);
        }
        LOADCI(Cc - 1, 1); FMACI(0); FMACI(1);

        // ---- epilogue: cur = cur_old + relu(conv), vector stores ----
        if constexpr (TP == 4) {
            float2 r0 = unpack2(acc[0]), r1 = unpack2(acc[1]);
            float2 r2 = unpack2(acc[2]), r3 = unpack2(acc[3]);
            float4 e, o;
            e.x = old4[0].x + fmaxf(r0.x, 0.f);
            e.y = old4[0].y + fmaxf(r1.x, 0.f);
            e.z = old4[0].z + fmaxf(r2.x, 0.f);
            e.w = old4[0].w + fmaxf(r3.x, 0.f);
            o.x = old4[1].x + fmaxf(r0.y, 0.f);
            o.y = old4[1].y + fmaxf(r1.y, 0.f);
            o.z = old4[1].z + fmaxf(r2.y, 0.f);
            o.w = old4[1].w + fmaxf(r3.y, 0.f);
            *reinterpret_cast<float4*>(cur + oBase)           = e;
            *reinterpret_cast<float4*>(cur + oBase + CSTRIDE) = o;
        } else {
            float2 r0 = unpack2(acc[0]), r1 = unpack2(acc[1]);
            float2 e, o;
            e.x = old2[0].x + fmaxf(r0.x, 0.f);
            e.y = old2[0].y + fmaxf(r1.x, 0.f);
            o.x = old2[1].x + fmaxf(r0.y, 0.f);
            o.y = old2[1].y + fmaxf(r1.y, 0.f);
            *reinterpret_cast<float2*>(cur + oBase)           = e;
            *reinterpret_cast<float2*>(cur + oBase + CSTRIDE) = o;
        }
    }
}

// [b,c,R,C] -> [b,c,C,R], tiled 32x32.
__global__ __launch_bounds__(256)
void transpose_kernel(const float* __restrict__ src, float* __restrict__ dst,
                      int R, int C)
{
    __shared__ float t[32][33];
    const long plane = blockIdx.z;
    const float* s = src + plane * (long)R * C;
    float*       d = dst + plane * (long)R * C;
    const int c0 = blockIdx.x * 32, r0 = blockIdx.y * 32;
    const int x = threadIdx.x & 31, y = threadIdx.x >> 5;
#pragma unroll
    for (int i = 0; i < 32; i += 8)
        t[y + i][x] = s[(long)(r0 + y + i) * C + c0 + x];
    __syncthreads();
#pragma unroll
    for (int i = 0; i < 32; i += 8)
        d[(long)(c0 + y + i) * R + r0 + x] = t[x][y + i];
}

extern "C" void kernel_launch(void* const* d_in, const int* in_sizes, int n_in,
                              void* d_out, int out_size)
{
    const float* x       = (const float*)d_in[0];
    const float* w_down  = (const float*)d_in[1];
    const float* w_up    = (const float*)d_in[2];
    const float* w_right = (const float*)d_in[3];
    const float* w_left  = (const float*)d_in[4];
    float* out = (float*)d_out;

    const int SMEM_W = (W_FLOATS + Cc * 80) * 4;   // 205312 B
    const int SMEM_H = (W_FLOATS + Cc * 48) * 4;   // 188928 B
    cudaFuncSetAttribute((const void*)pass_kernel<4>,
                         cudaFuncAttributeMaxDynamicSharedMemorySize, SMEM_W);
    cudaFuncSetAttribute((const void*)pass_kernel<2>,
                         cudaFuncAttributeMaxDynamicSharedMemorySize, SMEM_H);

    void* barp = nullptr;  cudaGetSymbolAddress(&barp, g_bar);
    void* tmpp = nullptr;  cudaGetSymbolAddress(&tmpp, g_tmp);
    float* tmp = (float*)tmpp;

    cudaMemcpyAsync(out, x, (size_t)Bb * BSTRIDE * sizeof(float),
                    cudaMemcpyDeviceToDevice);

    dim3 blk(256);
    dim3 gridW(Ww / 64, Cc / 32, Bb);   // conv along W, TP=4
    dim3 gridH(Hh / 32, Cc / 32, Bb);   // conv along H (transposed), TP=2

    // Pass 1: down. [b,c,h,w]: conv axis w (L=256), rec over h (SQ=256).
    cudaMemsetAsync(barp, 0, sizeof(unsigned) * Bb * 2);
    pass_kernel<4><<<gridW, blk, SMEM_W>>>(out, w_down, 0, +1, Hh, Ww, Ww);

    // Pass 2: up.
    cudaMemsetAsync(barp, 0, sizeof(unsigned) * Bb * 2);
    pass_kernel<4><<<gridW, blk, SMEM_W>>>(out, w_up, Hh - 1, -1, Hh, Ww, Ww);

    // Transpose to [b,c,w,h]
    transpose_kernel<<<dim3(Ww / 32, Hh / 32, Bb * Cc), blk>>>(out, tmp, Hh, Ww);

    // Pass 3: right. conv axis h (L=128), rec over w (SQ=128).
    cudaMemsetAsync(barp, 0, sizeof(unsigned) * Bb * 2);
    pass_kernel<2><<<gridH, blk, SMEM_H>>>(tmp, w_right, 0, +1, Ww, Hh, Hh);

    // Pass 4: left.
    cudaMemsetAsync(barp, 0, sizeof(unsigned) * Bb * 2);
    pass_kernel<2><<<gridH, blk, SMEM_H>>>(tmp, w_left, Ww - 1, -1, Ww, Hh, Hh);

    // Transpose back to [b,c,h,w]
    transpose_kernel<<<dim3(Hh / 32, Ww / 32, Bb * Cc), blk>>>(tmp, out, Ww, Hh);
}

// round 8
// speedup vs baseline: 3.0422x; 1.0026x over previous
#include <cuda_runtime.h>

#define Cc 128
#define Hh 128
#define Ww 256
#define Bb 8
#define Kk 9
#define CSTRIDE (Hh * Ww)          // 32768
#define BSTRIDE (Cc * Hh * Ww)     // 4194304

typedef unsigned long long ull;

// Per-tile completion counters: g_cnt[b][px][s] counts co-blocks (0..4) that
// have finished writing row s of p-block px for batch b. Reset per pass.
__device__ unsigned g_cnt[Bb][4][256];
// Transposed-state scratch: [b][c][w][h]
__device__ float g_tmp[(size_t)Bb * BSTRIDE];

// ---------- f32x2 helpers ----------
__device__ __forceinline__ ull splat2(float v) {
    ull r;
    asm("mov.b64 %0, {%1, %1};" : "=l"(r) : "f"(v));
    return r;
}
__device__ __forceinline__ void fma2(ull& d, ull a, ull b) {
    asm("fma.rn.f32x2 %0, %1, %2, %0;" : "+l"(d) : "l"(a), "l"(b));
}
__device__ __forceinline__ float2 unpack2(ull v) {
    float2 f;
    asm("mov.b64 {%0, %1}, %2;" : "=f"(f.x), "=f"(f.y) : "l"(v));
    return f;
}
__device__ __forceinline__ unsigned ld_cg_u32(const unsigned* p) {
    unsigned v;
    asm volatile("ld.global.cg.u32 %0, [%1];" : "=r"(v) : "l"(p));
    return v;
}

// Paired-weight SMEM layout: per cg (16 co-pairs), per ci: 20 floats
// (9 (co_even,co_odd) pairs + 2 pad). cg stride padded by 8 floats.
#define WCI_STRIDE 20
#define WCG_STRIDE (128 * WCI_STRIDE + 8)   // 2568 floats
#define W_FLOATS   (16 * WCG_STRIDE)        // 41088

// Persistent directional pass with neighbor-only dataflow sync.
// conv axis contiguous (length L), recurrence axis stride SQ from q0 step dq,
// nq rows. CTA = 256 thr = 16 pg x 16 cg; thread computes co-pair x TP p.
template <int TP>
__global__ __launch_bounds__(256)
void pass_kernel(float* __restrict__ state, const float* __restrict__ wt,
                 int q0, int dq, int nq, int L, int SQ)
{
    constexpr int PT  = 16 * TP;       // 64 (W-pass) or 32 (H-pass)
    constexpr int WIN = PT + 16;       // padded +-8, 16B-aligned rows
    constexpr int NV4 = WIN / 4;       // float4 slots per ci row
    constexpr int NW  = TP + 8;        // per-thread window floats

    extern __shared__ float sm[];
    float* s_w  = sm;
    float* s_in = sm + W_FLOATS;       // [128ci][WIN]

    const int tid = threadIdx.x;
    const int pg  = tid & 15;
    const int cg  = tid >> 4;

    const int px  = blockIdx.x;
    const int p0  = px * PT;
    const int co0 = blockIdx.y * 32;
    const int b   = blockIdx.z;
    const int npx = gridDim.x;         // 4
    float* base = state + (long)b * BSTRIDE;

    // ---- stage paired weights once per pass ----
    for (int idx = tid; idx < 16 * 128 * Kk; idx += 256) {
        int cgi = idx / (128 * Kk);
        int r   = idx - cgi * (128 * Kk);
        int ci  = r / Kk;
        int k   = r - ci * Kk;
        const float* g = wt + (long)(co0 + cgi * 2) * (Cc * Kk) + ci * Kk + k;
        float* dst = s_w + cgi * WCG_STRIDE + ci * WCI_STRIDE + k * 2;
        dst[0] = g[0];
        dst[1] = g[Cc * Kk];
    }
    __syncthreads();

    const float* wrow = s_w + cg * WCG_STRIDE;

    for (int s = 1; s < nq; s++) {
        // ---- wait for the 3 neighbor p-blocks of row s-1 (row 0 is free) ----
        if (s > 1) {
            if (tid < 3) {
                const int pxn = px + tid - 1;
                if (pxn >= 0 && pxn < npx) {
                    const unsigned* c = &g_cnt[b][pxn][s - 1];
                    while (ld_cg_u32(c) < 4u) __nanosleep(20);
                }
            }
            __syncthreads();
            __threadfence();   // acquire: order window loads after flag observe
        }

        const int q = q0 + s * dq;
        const float* prev = base + (long)(q - dq) * SQ;
        float*       cur  = base + (long)q * SQ;

        // ---- stage prev-row window, float4-vectorized ----
        for (int idx = tid; idx < Cc * NV4; idx += 256) {
            const int ci = idx / NV4;
            const int c4 = idx - ci * NV4;
            const int p  = p0 - 8 + c4 * 4;
            const float* src = prev + (long)ci * CSTRIDE + p;
            float4 v;
            if (p >= 0 && p + 4 <= L) {
                v = __ldcg(reinterpret_cast<const float4*>(src));
            } else {
                v.x = (unsigned)(p + 0) < (unsigned)L ? __ldcg(src + 0) : 0.f;
                v.y = (unsigned)(p + 1) < (unsigned)L ? __ldcg(src + 1) : 0.f;
                v.z = (unsigned)(p + 2) < (unsigned)L ? __ldcg(src + 2) : 0.f;
                v.w = (unsigned)(p + 3) < (unsigned)L ? __ldcg(src + 3) : 0.f;
            }
            reinterpret_cast<float4*>(s_in)[idx] = v;
        }

        // ---- prefetch cur_old (this CTA's exclusive addresses) ----
        const long oBase = (long)(co0 + cg * 2) * CSTRIDE + p0 + pg * TP;
        float4 old4[2]; float2 old2[2];
        if constexpr (TP == 4) {
            old4[0] = __ldcg(reinterpret_cast<const float4*>(cur + oBase));
            old4[1] = __ldcg(reinterpret_cast<const float4*>(cur + oBase + CSTRIDE));
        } else {
            old2[0] = __ldcg(reinterpret_cast<const float2*>(cur + oBase));
            old2[1] = __ldcg(reinterpret_cast<const float2*>(cur + oBase + CSTRIDE));
        }
        __syncthreads();

        // ---- software-pipelined compute over ci ----
        float vb[2][NW];
        ull   wb[2][9];

        auto LOADCI = [&](int ci, int slot) {
            if constexpr (TP == 4) {
                const float4* s4 =
                    reinterpret_cast<const float4*>(&s_in[ci * WIN + pg * 4 + 4]);
                float4 a = s4[0], b2 = s4[1], c2 = s4[2];
                vb[slot][0]=a.x;  vb[slot][1]=a.y;  vb[slot][2]=a.z;  vb[slot][3]=a.w;
                vb[slot][4]=b2.x; vb[slot][5]=b2.y; vb[slot][6]=b2.z; vb[slot][7]=b2.w;
                vb[slot][8]=c2.x; vb[slot][9]=c2.y; vb[slot][10]=c2.z; vb[slot][11]=c2.w;
            } else {
                const float2* s2 =
                    reinterpret_cast<const float2*>(&s_in[ci * WIN + pg * 2 + 4]);
#pragma unroll
                for (int j = 0; j < 5; j++) {
                    float2 t = s2[j];
                    vb[slot][2 * j] = t.x; vb[slot][2 * j + 1] = t.y;
                }
            }
            const float* wp = wrow + ci * WCI_STRIDE;
            const ulonglong2* w2 = reinterpret_cast<const ulonglong2*>(wp);
            ulonglong2 qa = w2[0], qb = w2[1], qc = w2[2], qd = w2[3];
            wb[slot][0]=qa.x; wb[slot][1]=qa.y; wb[slot][2]=qb.x; wb[slot][3]=qb.y;
            wb[slot][4]=qc.x; wb[slot][5]=qc.y; wb[slot][6]=qd.x; wb[slot][7]=qd.y;
            wb[slot][8]=reinterpret_cast<const ull*>(wp)[8];   // k=8 pair
        };

        ull acc[TP];
#pragma unroll
        for (int pt = 0; pt < TP; pt++) acc[pt] = 0ull;

        auto FMACI = [&](int slot) {
            ull sv[NW];
#pragma unroll
            for (int j = 0; j < NW; j++) sv[j] = splat2(vb[slot][j]);
#pragma unroll
            for (int k = 0; k < Kk; k++)
#pragma unroll
                for (int pt = 0; pt < TP; pt++)
                    fma2(acc[pt], wb[slot][k], sv[pt + k]);
        };

        LOADCI(0, 0);
        for (int ci = 0; ci + 2 < Cc; ci += 2) {
            LOADCI(ci + 1, 1); FMACI(0);
            LOADCI(ci + 2, 0); FMACI(1);
        }
        LOADCI(Cc - 1, 1); FMACI(0); FMACI(1);

        // ---- epilogue: cur = cur_old + relu(conv), vector stores ----
        if constexpr (TP == 4) {
            float2 r0 = unpack2(acc[0]), r1 = unpack2(acc[1]);
            float2 r2 = unpack2(acc[2]), r3 = unpack2(acc[3]);
            float4 e, o;
            e.x = old4[0].x + fmaxf(r0.x, 0.f);
            e.y = old4[0].y + fmaxf(r1.x, 0.f);
            e.z = old4[0].z + fmaxf(r2.x, 0.f);
            e.w = old4[0].w + fmaxf(r3.x, 0.f);
            o.x = old4[1].x + fmaxf(r0.y, 0.f);
            o.y = old4[1].y + fmaxf(r1.y, 0.f);
            o.z = old4[1].z + fmaxf(r2.y, 0.f);
            o.w = old4[1].w + fmaxf(r3.y, 0.f);
            *reinterpret_cast<float4*>(cur + oBase)           = e;
            *reinterpret_cast<float4*>(cur + oBase + CSTRIDE) = o;
        } else {
            float2 r0 = unpack2(acc[0]), r1 = unpack2(acc[1]);
            float2 e, o;
            e.x = old2[0].x + fmaxf(r0.x, 0.f);
            e.y = old2[0].y + fmaxf(r1.x, 0.f);
            o.x = old2[1].x + fmaxf(r0.y, 0.f);
            o.y = old2[1].y + fmaxf(r1.y, 0.f);
            *reinterpret_cast<float2*>(cur + oBase)           = e;
            *reinterpret_cast<float2*>(cur + oBase + CSTRIDE) = o;
        }

        // ---- publish this tile of row s ----
        __syncthreads();
        if (tid == 0) {
            __threadfence();
            atomicAdd(&g_cnt[b][px][s], 1u);
        }
    }
}

// [b,c,R,C] -> [b,c,C,R], tiled 32x32.
__global__ __launch_bounds__(256)
void transpose_kernel(const float* __restrict__ src, float* __restrict__ dst,
                      int R, int C)
{
    __shared__ float t[32][33];
    const long plane = blockIdx.z;
    const float* s = src + plane * (long)R * C;
    float*       d = dst + plane * (long)R * C;
    const int c0 = blockIdx.x * 32, r0 = blockIdx.y * 32;
    const int x = threadIdx.x & 31, y = threadIdx.x >> 5;
#pragma unroll
    for (int i = 0; i < 32; i += 8)
        t[y + i][x] = s[(long)(r0 + y + i) * C + c0 + x];
    __syncthreads();
#pragma unroll
    for (int i = 0; i < 32; i += 8)
        d[(long)(c0 + y + i) * R + r0 + x] = t[x][y + i];
}

extern "C" void kernel_launch(void* const* d_in, const int* in_sizes, int n_in,
                              void* d_out, int out_size)
{
    const float* x       = (const float*)d_in[0];
    const float* w_down  = (const float*)d_in[1];
    const float* w_up    = (const float*)d_in[2];
    const float* w_right = (const float*)d_in[3];
    const float* w_left  = (const float*)d_in[4];
    float* out = (float*)d_out;

    const int SMEM_W = (W_FLOATS + Cc * 80) * 4;   // 205312 B
    const int SMEM_H = (W_FLOATS + Cc * 48) * 4;   // 188928 B
    cudaFuncSetAttribute((const void*)pass_kernel<4>,
                         cudaFuncAttributeMaxDynamicSharedMemorySize, SMEM_W);
    cudaFuncSetAttribute((const void*)pass_kernel<2>,
                         cudaFuncAttributeMaxDynamicSharedMemorySize, SMEM_H);

    void* cntp = nullptr;  cudaGetSymbolAddress(&cntp, g_cnt);
    void* tmpp = nullptr;  cudaGetSymbolAddress(&tmpp, g_tmp);
    float* tmp = (float*)tmpp;
    const size_t CNT_BYTES = sizeof(unsigned) * Bb * 4 * 256;

    cudaMemcpyAsync(out, x, (size_t)Bb * BSTRIDE * sizeof(float),
                    cudaMemcpyDeviceToDevice);

    dim3 blk(256);
    dim3 gridW(Ww / 64, Cc / 32, Bb);   // conv along W, TP=4
    dim3 gridH(Hh / 32, Cc / 32, Bb);   // conv along H (transposed), TP=2

    // Pass 1: down. [b,c,h,w]: conv axis w (L=256), rec over h (SQ=256).
    cudaMemsetAsync(cntp, 0, CNT_BYTES);
    pass_kernel<4><<<gridW, blk, SMEM_W>>>(out, w_down, 0, +1, Hh, Ww, Ww);

    // Pass 2: up.
    cudaMemsetAsync(cntp, 0, CNT_BYTES);
    pass_kernel<4><<<gridW, blk, SMEM_W>>>(out, w_up, Hh - 1, -1, Hh, Ww, Ww);

    // Transpose to [b,c,w,h]
    transpose_kernel<<<dim3(Ww / 32, Hh / 32, Bb * Cc), blk>>>(out, tmp, Hh, Ww);

    // Pass 3: right. conv axis h (L=128), rec over w (SQ=128).
    cudaMemsetAsync(cntp, 0, CNT_BYTES);
    pass_kernel<2><<<gridH, blk, SMEM_H>>>(tmp, w_right, 0, +1, Ww, Hh, Hh);

    // Pass 4: left.
    cudaMemsetAsync(cntp, 0, CNT_BYTES);
    pass_kernel<2><<<gridH, blk, SMEM_H>>>(tmp, w_left, Ww - 1, -1, Ww, Hh, Hh);

    // Transpose back to [b,c,h,w]
    transpose_kernel<<<dim3(Hh / 32, Ww / 32, Bb * Cc), blk>>>(tmp, out, Ww, Hh);
}

// round 9
// speedup vs baseline: 3.0949x; 1.0173x over previous
#include <cuda_runtime.h>

#define Cc 128
#define Hh 128
#define Ww 256
#define Bb 8
#define Kk 9
#define CSTRIDE (Hh * Ww)          // 32768
#define BSTRIDE (Cc * Hh * Ww)     // 4194304

typedef unsigned long long ull;

// Per-tile completion counters: g_cnt[b][px][s] counts co-blocks (0..4) done
// writing row s of p-block px for batch b. Reset per pass.
__device__ unsigned g_cnt[Bb][4][256];
// Transposed-state scratch: [b][c][w][h]
__device__ float g_tmp[(size_t)Bb * BSTRIDE];

// ---------- f32x2 helpers ----------
__device__ __forceinline__ void fma2(ull& d, ull a, ull b) {
    asm("fma.rn.f32x2 %0, %1, %2, %0;" : "+l"(d) : "l"(a), "l"(b));
}
__device__ __forceinline__ void add2(ull& d, ull a) {
    asm("add.rn.f32x2 %0, %0, %1;" : "+l"(d) : "l"(a));
}
__device__ __forceinline__ float2 unpack2(ull v) {
    float2 f;
    asm("mov.b64 {%0, %1}, %2;" : "=f"(f.x), "=f"(f.y) : "l"(v));
    return f;
}
__device__ __forceinline__ unsigned ld_cg_u32(const unsigned* p) {
    unsigned v;
    asm volatile("ld.global.cg.u32 %0, [%1];" : "=r"(v) : "l"(p));
    return v;
}

// Persistent directional pass, neighbor-only dataflow sync, ci-paired FFMA2.
//
// Decomposition: 512 threads = SPLIT ci-groups x CGC co-groups x PGC p-groups.
//   pg = tid & (PGC-1); cg = (tid/PGC) % CGC; sp = tid / (PGC*CGC).
// Thread computes COT co x TP p outputs, reducing over its ci2 slice
// [sp*64/SPLIT, ...). Partial sums combined through s_red by sp==0 group.
//
// acc u64 lanes pack (even-ci partial, odd-ci partial); conv = lane0+lane1.
// Weights in SMEM as u64 (w[co][2ci2][k], w[co][2ci2+1][k]) - staged once.
// Window in SMEM as u64 (prev[2ci2][p], prev[2ci2+1][p]).
template <int TP, int COT, int SPLIT>
__global__ __launch_bounds__(512)
void pass_kernel(float* __restrict__ state, const float* __restrict__ wt,
                 int q0, int dq, int nq, int L, int SQ)
{
    constexpr int CGC    = 32 / COT;            // co-groups
    constexpr int PGC    = 512 / SPLIT / CGC;   // p-groups (16 for both cfgs)
    constexpr int PT     = PGC * TP;            // CTA p extent (W:64, H:32)
    constexpr int WIN    = PT + 16;             // u64 window entries per ci2
    constexpr int NW     = TP + 8;              // per-thread window u64s
    constexpr int G      = 512 / SPLIT;         // threads per ci-group
    constexpr int ROWU64 = Kk * COT;            // weight u64 per (cg,ci2): 18/36
    constexpr int WU64   = CGC * 64 * ROWU64;   // 18432 u64 both cfgs
    constexpr int CI2PER = 64 / SPLIT;          // ci2 per split group

    extern __shared__ ull smu[];
    ull* s_w   = smu;                  // paired weights
    ull* s_in  = smu + WU64;           // [64 ci2][WIN]
    ull* s_red = s_in + 64 * WIN;      // [(SPLIT-1)*G][COT*TP]

    const int tid = threadIdx.x;
    const int pg  = tid & (PGC - 1);
    const int cg  = (tid / PGC) % CGC;
    const int sp  = tid / G;

    const int px  = blockIdx.x;
    const int p0  = px * PT;
    const int co0 = blockIdx.y * 32;
    const int b   = blockIdx.z;
    const int npx = gridDim.x;
    float* base = state + (long)b * BSTRIDE;

    // ---- stage paired weights once per pass ----
    {
        float* s_wf = reinterpret_cast<float*>(s_w);
        for (int idx = tid; idx < CGC * 64 * Kk * COT; idx += 512) {
            int c   = idx % COT;
            int k   = (idx / COT) % Kk;
            int ci2 = (idx / (COT * Kk)) % 64;
            int cgi = idx / (COT * Kk * 64);
            int co  = co0 + cgi * COT + c;
            long u  = (long)cgi * (64 * ROWU64) + ci2 * ROWU64 + k * COT + c;
            s_wf[u * 2 + 0] = wt[(long)co * (Cc * Kk) + (2 * ci2) * Kk + k];
            s_wf[u * 2 + 1] = wt[(long)co * (Cc * Kk) + (2 * ci2 + 1) * Kk + k];
        }
    }
    __syncthreads();

    const ull* wbase = s_w + (long)cg * (64 * ROWU64);
    const int ci2lo = sp * CI2PER;

    for (int s = 1; s < nq; s++) {
        // ---- wait for the 3 neighbor p-blocks' row s-1 (row 0 is free) ----
        if (s > 1) {
            if (tid < 3) {
                const int pxn = px + tid - 1;
                if (pxn >= 0 && pxn < npx) {
                    const unsigned* c = &g_cnt[b][pxn][s - 1];
                    while (ld_cg_u32(c) < 4u) __nanosleep(20);
                }
            }
            __syncthreads();
            __threadfence();   // acquire
        }

        const int q = q0 + s * dq;
        const float* prev = base + (long)(q - dq) * SQ;
        float*       cur  = base + (long)q * SQ;

        // ---- stage window: s_in[ci2][pl] = (prev[2ci2][p], prev[2ci2+1][p]) ----
        {
            constexpr int Q = WIN / 4;
            float4* s_in4 = reinterpret_cast<float4*>(s_in);
            for (int idx = tid; idx < 64 * Q; idx += 512) {
                const int ci2 = idx / Q;
                const int pl  = (idx - ci2 * Q) * 4;
                const int p   = p0 - 8 + pl;
                const float* sa = prev + (long)(2 * ci2)     * CSTRIDE + p;
                const float* sb = prev + (long)(2 * ci2 + 1) * CSTRIDE + p;
                float4 a, bb;
                if (p >= 0 && p + 4 <= L) {
                    a  = __ldcg(reinterpret_cast<const float4*>(sa));
                    bb = __ldcg(reinterpret_cast<const float4*>(sb));
                } else {
                    a.x = (unsigned)(p+0) < (unsigned)L ? __ldcg(sa+0) : 0.f;
                    a.y = (unsigned)(p+1) < (unsigned)L ? __ldcg(sa+1) : 0.f;
                    a.z = (unsigned)(p+2) < (unsigned)L ? __ldcg(sa+2) : 0.f;
                    a.w = (unsigned)(p+3) < (unsigned)L ? __ldcg(sa+3) : 0.f;
                    bb.x = (unsigned)(p+0) < (unsigned)L ? __ldcg(sb+0) : 0.f;
                    bb.y = (unsigned)(p+1) < (unsigned)L ? __ldcg(sb+1) : 0.f;
                    bb.z = (unsigned)(p+2) < (unsigned)L ? __ldcg(sb+2) : 0.f;
                    bb.w = (unsigned)(p+3) < (unsigned)L ? __ldcg(sb+3) : 0.f;
                }
                const int f4i = (ci2 * WIN + pl) >> 1;
                s_in4[f4i + 0] = make_float4(a.x, bb.x, a.y, bb.y);
                s_in4[f4i + 1] = make_float4(a.z, bb.z, a.w, bb.w);
            }
        }

        // ---- prefetch cur_old (sp0 only; exclusive addresses) ----
        const long oRow = (long)(co0 + cg * COT) * CSTRIDE + p0 + pg * TP;
        float4 old4[COT];
        float2 old2[COT];
        if (sp == 0) {
#pragma unroll
            for (int c = 0; c < COT; c++) {
                const float* op = cur + oRow + (long)c * CSTRIDE;
                if constexpr (TP == 4)
                    old4[c] = __ldcg(reinterpret_cast<const float4*>(op));
                else
                    old2[c] = __ldcg(reinterpret_cast<const float2*>(op));
            }
        }
        __syncthreads();

        // ---- compute over own ci2 slice ----
        ull acc[COT][TP];
#pragma unroll
        for (int c = 0; c < COT; c++)
#pragma unroll
            for (int pt = 0; pt < TP; pt++) acc[c][pt] = 0ull;

        for (int i = 0; i < CI2PER; i++) {
            const int ci2 = ci2lo + i;
            // window u64s (16B-aligned: pg*TP+4 even)
            ull win[NW];
            {
                const ulonglong2* w2 = reinterpret_cast<const ulonglong2*>(
                    s_in + (long)ci2 * WIN + pg * TP + 4);
#pragma unroll
                for (int j = 0; j < NW / 2; j++) {
                    ulonglong2 t = w2[j];
                    win[2 * j] = t.x; win[2 * j + 1] = t.y;
                }
            }
            const ull* wrow = wbase + (long)ci2 * ROWU64;
#pragma unroll
            for (int k = 0; k < Kk; k++) {
#pragma unroll
                for (int c2 = 0; c2 < COT / 2; c2++) {
                    ulonglong2 w = *reinterpret_cast<const ulonglong2*>(
                        wrow + k * COT + c2 * 2);
#pragma unroll
                    for (int pt = 0; pt < TP; pt++) {
                        fma2(acc[c2 * 2 + 0][pt], w.x, win[pt + k]);
                        fma2(acc[c2 * 2 + 1][pt], w.y, win[pt + k]);
                    }
                }
            }
        }

        // ---- cross-split reduction ----
        if (sp > 0) {
            ull* r = s_red + (long)((sp - 1) * G + (tid & (G - 1))) * (COT * TP);
#pragma unroll
            for (int c = 0; c < COT; c++)
#pragma unroll
                for (int pt = 0; pt < TP; pt++) r[c * TP + pt] = acc[c][pt];
        }
        __syncthreads();

        if (sp == 0) {
#pragma unroll
            for (int j = 0; j < SPLIT - 1; j++) {
                const ull* r = s_red + (long)(j * G + tid) * (COT * TP);
#pragma unroll
                for (int c = 0; c < COT; c++)
#pragma unroll
                    for (int pt = 0; pt < TP; pt++) add2(acc[c][pt], r[c * TP + pt]);
            }
            // ---- epilogue: cur = cur_old + relu(lane0+lane1) ----
#pragma unroll
            for (int c = 0; c < COT; c++) {
                float* op = cur + oRow + (long)c * CSTRIDE;
                if constexpr (TP == 4) {
                    float4 e;
                    float2 t0 = unpack2(acc[c][0]), t1 = unpack2(acc[c][1]);
                    float2 t2 = unpack2(acc[c][2]), t3 = unpack2(acc[c][3]);
                    e.x = old4[c].x + fmaxf(t0.x + t0.y, 0.f);
                    e.y = old4[c].y + fmaxf(t1.x + t1.y, 0.f);
                    e.z = old4[c].z + fmaxf(t2.x + t2.y, 0.f);
                    e.w = old4[c].w + fmaxf(t3.x + t3.y, 0.f);
                    *reinterpret_cast<float4*>(op) = e;
                } else {
                    float2 e;
                    float2 t0 = unpack2(acc[c][0]), t1 = unpack2(acc[c][1]);
                    e.x = old2[c].x + fmaxf(t0.x + t0.y, 0.f);
                    e.y = old2[c].y + fmaxf(t1.x + t1.y, 0.f);
                    *reinterpret_cast<float2*>(op) = e;
                }
            }
        }

        // ---- publish this tile of row s ----
        __syncthreads();
        if (tid == 0) {
            __threadfence();
            atomicAdd(&g_cnt[b][px][s], 1u);
        }
    }
}

// [b,c,R,C] -> [b,c,C,R], tiled 32x32.
__global__ __launch_bounds__(256)
void transpose_kernel(const float* __restrict__ src, float* __restrict__ dst,
                      int R, int C)
{
    __shared__ float t[32][33];
    const long plane = blockIdx.z;
    const float* s = src + plane * (long)R * C;
    float*       d = dst + plane * (long)R * C;
    const int c0 = blockIdx.x * 32, r0 = blockIdx.y * 32;
    const int x = threadIdx.x & 31, y = threadIdx.x >> 5;
#pragma unroll
    for (int i = 0; i < 32; i += 8)
        t[y + i][x] = s[(long)(r0 + y + i) * C + c0 + x];
    __syncthreads();
#pragma unroll
    for (int i = 0; i < 32; i += 8)
        d[(long)(c0 + y + i) * R + r0 + x] = t[x][y + i];
}

extern "C" void kernel_launch(void* const* d_in, const int* in_sizes, int n_in,
                              void* d_out, int out_size)
{
    const float* x       = (const float*)d_in[0];
    const float* w_down  = (const float*)d_in[1];
    const float* w_up    = (const float*)d_in[2];
    const float* w_right = (const float*)d_in[3];
    const float* w_left  = (const float*)d_in[4];
    float* out = (float*)d_out;

    // SMEM sizes (u64 counts x 8B)
    const int SMEM_W = (18432 + 64 * 80 + 256 * 8) * 8;   // 204800 B
    const int SMEM_H = (18432 + 64 * 48 + 384 * 8) * 8;   // 196608 B
    cudaFuncSetAttribute((const void*)pass_kernel<4, 2, 2>,
                         cudaFuncAttributeMaxDynamicSharedMemorySize, SMEM_W);
    cudaFuncSetAttribute((const void*)pass_kernel<2, 4, 4>,
                         cudaFuncAttributeMaxDynamicSharedMemorySize, SMEM_H);

    void* cntp = nullptr;  cudaGetSymbolAddress(&cntp, g_cnt);
    void* tmpp = nullptr;  cudaGetSymbolAddress(&tmpp, g_tmp);
    float* tmp = (float*)tmpp;
    const size_t CNT_BYTES = sizeof(unsigned) * Bb * 4 * 256;

    cudaMemcpyAsync(out, x, (size_t)Bb * BSTRIDE * sizeof(float),
                    cudaMemcpyDeviceToDevice);

    dim3 blk(512);
    dim3 gridW(Ww / 64, Cc / 32, Bb);   // conv along W: TP=4, COT=2, SPLIT=2
    dim3 gridH(Hh / 32, Cc / 32, Bb);   // conv along H: TP=2, COT=4, SPLIT=4

    // Pass 1: down. [b,c,h,w]: conv axis w (L=256), rec over h (SQ=256).
    cudaMemsetAsync(cntp, 0, CNT_BYTES);
    pass_kernel<4, 2, 2><<<gridW, blk, SMEM_W>>>(out, w_down, 0, +1, Hh, Ww, Ww);

    // Pass 2: up.
    cudaMemsetAsync(cntp, 0, CNT_BYTES);
    pass_kernel<4, 2, 2><<<gridW, blk, SMEM_W>>>(out, w_up, Hh - 1, -1, Hh, Ww, Ww);

    // Transpose to [b,c,w,h]
    transpose_kernel<<<dim3(Ww / 32, Hh / 32, Bb * Cc), dim3(256)>>>(out, tmp, Hh, Ww);

    // Pass 3: right. conv axis h (L=128), rec over w (SQ=128).
    cudaMemsetAsync(cntp, 0, CNT_BYTES);
    pass_kernel<2, 4, 4><<<gridH, blk, SMEM_H>>>(tmp, w_right, 0, +1, Ww, Hh, Hh);

    // Pass 4: left.
    cudaMemsetAsync(cntp, 0, CNT_BYTES);
    pass_kernel<2, 4, 4><<<gridH, blk, SMEM_H>>>(tmp, w_left, Ww - 1, -1, Ww, Hh, Hh);

    // Transpose back to [b,c,h,w]
    transpose_kernel<<<dim3(Hh / 32, Ww / 32, Bb * Cc), dim3(256)>>>(tmp, out, Ww, Hh);
}

// round 10
// speedup vs baseline: 3.2026x; 1.0348x over previous
#include <cuda_runtime.h>

#define Cc 128
#define Hh 128
#define Ww 256
#define Bb 8
#define Kk 9
#define CSTRIDE (Hh * Ww)          // 32768
#define BSTRIDE (Cc * Hh * Ww)     // 4194304

typedef unsigned long long ull;

// Per-(batch, p-block, co-block, step) completion flags. Reset per pass.
__device__ unsigned g_flag[Bb][4][4][256];
// Transposed-state scratch: [b][c][w][h]
__device__ float g_tmp[(size_t)Bb * BSTRIDE];

// ---------- f32x2 helpers ----------
__device__ __forceinline__ void fma2(ull& d, ull a, ull b) {
    asm("fma.rn.f32x2 %0, %1, %2, %0;" : "+l"(d) : "l"(a), "l"(b));
}
__device__ __forceinline__ float2 unpack2(ull v) {
    float2 f;
    asm("mov.b64 {%0, %1}, %2;" : "=f"(f.x), "=f"(f.y) : "l"(v));
    return f;
}
__device__ __forceinline__ unsigned ld_cg_u32(const unsigned* p) {
    unsigned v;
    asm volatile("ld.global.cg.u32 %0, [%1];" : "=r"(v) : "l"(p));
    return v;
}
__device__ __forceinline__ void group_bar(int id, int cnt) {
    asm volatile("bar.sync %0, %1;" :: "r"(id), "r"(cnt) : "memory");
}

// Persistent directional pass; 1024 threads = SPLIT ci-groups of G threads.
// Group sp owns ci2 slice [sp*CI2PER, ...), waits only on its producers'
// flags, stages its own window slice, computes partials; one CTA-wide
// __syncthreads before cross-split reduction; sp0 reduces + epilogue +
// publishes while other groups proceed to step s+1.
// acc u64 lanes pack (even-ci, odd-ci) partials; conv = lane0+lane1.
template <int TP, int COT, int SPLIT>
__global__ __launch_bounds__(1024, 1)
void pass_kernel(float* __restrict__ state, const float* __restrict__ wt,
                 int q0, int dq, int nq, int L, int SQ)
{
    constexpr int CGC    = 32 / COT;             // co-groups per group
    constexpr int PGC    = 1024 / SPLIT / CGC;   // p-groups (16 both cfgs)
    constexpr int PT     = PGC * TP;             // CTA p extent (W:64, H:32)
    constexpr int WIN    = PT + 8;               // u64 window entries per ci2
    constexpr int NW     = TP + 8;               // per-thread window u64s
    constexpr int G      = 1024 / SPLIT;         // threads per ci-group
    constexpr int ROWU64 = Kk * COT;             // weight u64 per (cg,ci2)
    constexpr int WU64   = CGC * 64 * ROWU64;    // 18432 u64 both cfgs
    constexpr int CI2PER = 64 / SPLIT;
    constexpr int CHUNKS = WIN / 4;              // float4 stage chunks per row
    constexpr int ACCN   = COT * TP;             // 8

    extern __shared__ ull smu[];
    ull*   s_w   = smu;                          // paired weights
    ull*   s_in  = smu + WU64;                   // [64 ci2][WIN]
    float* s_red = reinterpret_cast<float*>(s_in + 64 * WIN); // [(SPLIT-1)*G][8]

    const int tid  = threadIdx.x;
    const int sp   = tid / G;
    const int gtid = tid & (G - 1);
    const int pg   = gtid & (PGC - 1);
    const int cg   = gtid / PGC;

    const int px  = blockIdx.x;
    const int cby = blockIdx.y;
    const int b   = blockIdx.z;
    const int p0  = px * PT;
    const int co0 = cby * 32;
    const int npx = gridDim.x;
    float* base = state + (long)b * BSTRIDE;

    // ---- stage paired weights once per pass ----
    {
        float* s_wf = reinterpret_cast<float*>(s_w);
        for (int idx = tid; idx < CGC * 64 * Kk * COT; idx += 1024) {
            int c   = idx % COT;
            int k   = (idx / COT) % Kk;
            int ci2 = (idx / (COT * Kk)) % 64;
            int cgi = idx / (COT * Kk * 64);
            int co  = co0 + cgi * COT + c;
            long u  = (long)cgi * (64 * ROWU64) + ci2 * ROWU64 + k * COT + c;
            s_wf[u * 2 + 0] = wt[(long)co * (Cc * Kk) + (2 * ci2) * Kk + k];
            s_wf[u * 2 + 1] = wt[(long)co * (Cc * Kk) + (2 * ci2 + 1) * Kk + k];
        }
    }
    __syncthreads();

    const ull* wbase = s_w + (long)cg * (64 * ROWU64);
    const int ci2lo = sp * CI2PER;
    const int cbs   = ci2lo >> 4;     // producer co-block of this ci slice

    for (int s = 1; s < nq; s++) {
        const int q = q0 + s * dq;
        const float* prev = base + (long)(q - dq) * SQ;
        float*       cur  = base + (long)q * SQ;
        const long oBase = (long)(co0 + cg * COT) * CSTRIDE + p0 + pg * TP;

        // ---- prefetch cur_old (pass-stable; sp0 only) ----
        float4 old4[COT]; float2 old2[COT];
        if (sp == 0) {
#pragma unroll
            for (int c = 0; c < COT; c++) {
                const float* op = cur + oBase + (long)c * CSTRIDE;
                if constexpr (TP == 4)
                    old4[c] = __ldcg(reinterpret_cast<const float4*>(op));
                else
                    old2[c] = __ldcg(reinterpret_cast<const float2*>(op));
            }
        }

        // ---- wait for this slice's producers (plus own CTA for s_red guard) ----
        if (s > 1 && gtid < 4) {
            const unsigned* f = nullptr;
            if (gtid < 3) {
                int pxn = px + gtid - 1;
                if (pxn >= 0 && pxn < npx) f = &g_flag[b][pxn][cbs][s - 1];
            } else {
                f = &g_flag[b][px][cby][s - 1];
            }
            if (f) {
                while (ld_cg_u32(f) == 0u) __nanosleep(20);
                __threadfence();
            }
        }
        group_bar(sp + 1, G);

        // ---- stage own ci2 slice of the window ----
        for (int t = gtid; t < CI2PER * CHUNKS; t += G) {
            const int ci2 = ci2lo + t / CHUNKS;
            const int c4  = t % CHUNKS;
            const int p   = p0 - 4 + c4 * 4;
            const float* sa = prev + (long)(2 * ci2) * CSTRIDE + p;
            const float* sb = sa + CSTRIDE;
            float4 a, bb;
            if (p >= 0 && p + 4 <= L) {
                a  = __ldcg(reinterpret_cast<const float4*>(sa));
                bb = __ldcg(reinterpret_cast<const float4*>(sb));
            } else {
                a.x = (unsigned)(p+0) < (unsigned)L ? __ldcg(sa+0) : 0.f;
                a.y = (unsigned)(p+1) < (unsigned)L ? __ldcg(sa+1) : 0.f;
                a.z = (unsigned)(p+2) < (unsigned)L ? __ldcg(sa+2) : 0.f;
                a.w = (unsigned)(p+3) < (unsigned)L ? __ldcg(sa+3) : 0.f;
                bb.x = (unsigned)(p+0) < (unsigned)L ? __ldcg(sb+0) : 0.f;
                bb.y = (unsigned)(p+1) < (unsigned)L ? __ldcg(sb+1) : 0.f;
                bb.z = (unsigned)(p+2) < (unsigned)L ? __ldcg(sb+2) : 0.f;
                bb.w = (unsigned)(p+3) < (unsigned)L ? __ldcg(sb+3) : 0.f;
            }
            float4* s4 = reinterpret_cast<float4*>(s_in);
            const int f4i = (ci2 * WIN + c4 * 4) >> 1;
            s4[f4i + 0] = make_float4(a.x, bb.x, a.y, bb.y);
            s4[f4i + 1] = make_float4(a.z, bb.z, a.w, bb.w);
        }
        group_bar(sp + 1, G);

        // ---- compute over own ci2 slice (proven R8 inner loop) ----
        ull acc[COT][TP];
#pragma unroll
        for (int c = 0; c < COT; c++)
#pragma unroll
            for (int pt = 0; pt < TP; pt++) acc[c][pt] = 0ull;

#pragma unroll 2
        for (int i = 0; i < CI2PER; i++) {
            const int ci2 = ci2lo + i;
            ull win[NW];
            {
                const ulonglong2* w2 = reinterpret_cast<const ulonglong2*>(
                    s_in + (long)ci2 * WIN + pg * TP);
#pragma unroll
                for (int j = 0; j < NW / 2; j++) {
                    ulonglong2 t = w2[j];
                    win[2 * j] = t.x; win[2 * j + 1] = t.y;
                }
            }
            const ull* wrow = wbase + (long)ci2 * ROWU64;
#pragma unroll
            for (int k = 0; k < Kk; k++) {
#pragma unroll
                for (int c2 = 0; c2 < COT / 2; c2++) {
                    ulonglong2 w = *reinterpret_cast<const ulonglong2*>(
                        wrow + k * COT + c2 * 2);
#pragma unroll
                    for (int pt = 0; pt < TP; pt++) {
                        fma2(acc[c2 * 2 + 0][pt], w.x, win[pt + k]);
                        fma2(acc[c2 * 2 + 1][pt], w.y, win[pt + k]);
                    }
                }
            }
        }

        // ---- fold lanes to floats; sp>0 deposit partials ----
        float f[ACCN];
#pragma unroll
        for (int c = 0; c < COT; c++)
#pragma unroll
            for (int pt = 0; pt < TP; pt++) {
                float2 t = unpack2(acc[c][pt]);
                f[c * TP + pt] = t.x + t.y;
            }
        if (sp > 0) {
            float* r = s_red + (long)((sp - 1) * G + gtid) * ACCN;
            *reinterpret_cast<float4*>(r)     = make_float4(f[0], f[1], f[2], f[3]);
            *reinterpret_cast<float4*>(r + 4) = make_float4(f[4], f[5], f[6], f[7]);
        }
        __syncthreads();   // the ONLY CTA-wide barrier per step

        if (sp == 0) {
#pragma unroll
            for (int j = 0; j < SPLIT - 1; j++) {
                const float* r = s_red + (long)(j * G + gtid) * ACCN;
                float4 r0 = *reinterpret_cast<const float4*>(r);
                float4 r1 = *reinterpret_cast<const float4*>(r + 4);
                f[0] += r0.x; f[1] += r0.y; f[2] += r0.z; f[3] += r0.w;
                f[4] += r1.x; f[5] += r1.y; f[6] += r1.z; f[7] += r1.w;
            }
            // ---- epilogue: cur = cur_old + relu(conv) ----
#pragma unroll
            for (int c = 0; c < COT; c++) {
                float* op = cur + oBase + (long)c * CSTRIDE;
                if constexpr (TP == 4) {
                    float4 e;
                    e.x = old4[c].x + fmaxf(f[c * 4 + 0], 0.f);
                    e.y = old4[c].y + fmaxf(f[c * 4 + 1], 0.f);
                    e.z = old4[c].z + fmaxf(f[c * 4 + 2], 0.f);
                    e.w = old4[c].w + fmaxf(f[c * 4 + 3], 0.f);
                    *reinterpret_cast<float4*>(op) = e;
                } else {
                    float2 e;
                    e.x = old2[c].x + fmaxf(f[c * 2 + 0], 0.f);
                    e.y = old2[c].y + fmaxf(f[c * 2 + 1], 0.f);
                    *reinterpret_cast<float2*>(op) = e;
                }
            }
            group_bar(1, G);
            if (tid == 0) {
                __threadfence();
                atomicExch(&g_flag[b][px][cby][s], 1u);
            }
        }
    }
}

// [b,c,R,C] -> [b,c,C,R], tiled 32x32.
__global__ __launch_bounds__(256)
void transpose_kernel(const float* __restrict__ src, float* __restrict__ dst,
                      int R, int C)
{
    __shared__ float t[32][33];
    const long plane = blockIdx.z;
    const float* s = src + plane * (long)R * C;
    float*       d = dst + plane * (long)R * C;
    const int c0 = blockIdx.x * 32, r0 = blockIdx.y * 32;
    const int x = threadIdx.x & 31, y = threadIdx.x >> 5;
#pragma unroll
    for (int i = 0; i < 32; i += 8)
        t[y + i][x] = s[(long)(r0 + y + i) * C + c0 + x];
    __syncthreads();
#pragma unroll
    for (int i = 0; i < 32; i += 8)
        d[(long)(c0 + y + i) * R + r0 + x] = t[x][y + i];
}

extern "C" void kernel_launch(void* const* d_in, const int* in_sizes, int n_in,
                              void* d_out, int out_size)
{
    const float* x       = (const float*)d_in[0];
    const float* w_down  = (const float*)d_in[1];
    const float* w_up    = (const float*)d_in[2];
    const float* w_right = (const float*)d_in[3];
    const float* w_left  = (const float*)d_in[4];
    float* out = (float*)d_out;

    // SMEM: weights(18432 u64) + window(64*WIN u64) + s_red floats
    const int SMEM_W = 18432 * 8 + 64 * 72 * 8 + 3 * 256 * 8 * 4;  // 208896
    const int SMEM_H = 18432 * 8 + 64 * 40 * 8 + 7 * 128 * 8 * 4;  // 196608
    cudaFuncSetAttribute((const void*)pass_kernel<4, 2, 4>,
                         cudaFuncAttributeMaxDynamicSharedMemorySize, SMEM_W);
    cudaFuncSetAttribute((const void*)pass_kernel<2, 4, 8>,
                         cudaFuncAttributeMaxDynamicSharedMemorySize, SMEM_H);

    void* flagp = nullptr; cudaGetSymbolAddress(&flagp, g_flag);
    void* tmpp  = nullptr; cudaGetSymbolAddress(&tmpp, g_tmp);
    float* tmp = (float*)tmpp;
    const size_t FLAG_BYTES = sizeof(unsigned) * Bb * 4 * 4 * 256;

    cudaMemcpyAsync(out, x, (size_t)Bb * BSTRIDE * sizeof(float),
                    cudaMemcpyDeviceToDevice);

    dim3 blk(1024);
    dim3 gridW(Ww / 64, Cc / 32, Bb);   // conv along W: TP=4, COT=2, SPLIT=4
    dim3 gridH(Hh / 32, Cc / 32, Bb);   // conv along H: TP=2, COT=4, SPLIT=8

    // Pass 1: down. [b,c,h,w]: conv axis w (L=256), rec over h (SQ=256).
    cudaMemsetAsync(flagp, 0, FLAG_BYTES);
    pass_kernel<4, 2, 4><<<gridW, blk, SMEM_W>>>(out, w_down, 0, +1, Hh, Ww, Ww);

    // Pass 2: up.
    cudaMemsetAsync(flagp, 0, FLAG_BYTES);
    pass_kernel<4, 2, 4><<<gridW, blk, SMEM_W>>>(out, w_up, Hh - 1, -1, Hh, Ww, Ww);

    // Transpose to [b,c,w,h]
    transpose_kernel<<<dim3(Ww / 32, Hh / 32, Bb * Cc), dim3(256)>>>(out, tmp, Hh, Ww);

    // Pass 3: right. conv axis h (L=128), rec over w (SQ=128).
    cudaMemsetAsync(flagp, 0, FLAG_BYTES);
    pass_kernel<2, 4, 8><<<gridH, blk, SMEM_H>>>(tmp, w_right, 0, +1, Ww, Hh, Hh);

    // Pass 4: left.
    cudaMemsetAsync(flagp, 0, FLAG_BYTES);
    pass_kernel<2, 4, 8><<<gridH, blk, SMEM_H>>>(tmp, w_left, Ww - 1, -1, Ww, Hh, Hh);

    // Transpose back to [b,c,h,w]
    transpose_kernel<<<dim3(Hh / 32, Ww / 32, Bb * Cc), dim3(256)>>>(tmp, out, Ww, Hh);
}